// round 3
// baseline (speedup 1.0000x reference)
#include <cuda_runtime.h>

#define Tn 256
#define Bn 64
#define Dn 768
#define Rn 2048

// Scratch (static __device__ arrays: allocation-guard safe)
__device__ float g_P[(size_t)Tn * Rn * Bn];   // [t][r][b] : input projection + bias, 128 MB
__device__ float g_x0[Rn * Bn];               // state ping [r][b]
__device__ float g_x1[Rn * Bn];               // state pong [r][b]

// ---- packed f32x2 helpers (Blackwell sm_103a) ----
__device__ __forceinline__ unsigned long long pack2(float lo, float hi) {
    unsigned long long r;
    asm("mov.b64 %0, {%1, %2};" : "=l"(r) : "f"(lo), "f"(hi));
    return r;
}
__device__ __forceinline__ void unpack2(unsigned long long v, float& lo, float& hi) {
    asm("mov.b64 {%0, %1}, %2;" : "=f"(lo), "=f"(hi) : "l"(v));
}
__device__ __forceinline__ void ffma2(unsigned long long& d, unsigned long long a, unsigned long long b) {
    asm("fma.rn.f32x2 %0, %1, %2, %0;" : "+l"(d) : "l"(a), "l"(b));
}

// accurate-enough tanh independent of fast-math flags (~1e-6 rel)
__device__ __forceinline__ float tanh_acc(float x) {
    float ax = fabsf(x);
    float e  = __expf(-2.0f * ax);          // in (0,1]
    float r  = (1.0f - e) / (1.0f + e);     // tanh(|x|)
    return copysignf(r, x);
}

// ---------------------------------------------------------------------------
// init: xT[r][b] = initial_state[r]
// ---------------------------------------------------------------------------
__global__ void init_x_kernel(const float* __restrict__ init_state) {
    int i = blockIdx.x * blockDim.x + threadIdx.x;
    if (i < Rn * Bn) g_x0[i] = init_state[i >> 6];
}

// ---------------------------------------------------------------------------
// proj: g_P[t][r][b] = sum_d inp[t][b][d] * Win[r][d] + bias[r]
// grid (Rn/64, Tn), block 128. Tile 64b x 64r, micro 4b x 8r, packed f32x2.
// ---------------------------------------------------------------------------
__global__ __launch_bounds__(128) void proj_kernel(const float* __restrict__ inp,
                                                   const float* __restrict__ win,
                                                   const float* __restrict__ bias) {
    __shared__ __align__(16) float As[16][64];   // [k][b]
    __shared__ __align__(16) float Bs[16][64];   // [k][r]
    const int t  = blockIdx.y;
    const int rt = blockIdx.x;
    const int tid = threadIdx.x;
    const int tx = tid & 15;        // b-group: b = tx*4 + bb
    const int ty = tid >> 4;        // r-group: r = ty*8 + j  (0..7)

    unsigned long long acc[4][4];
#pragma unroll
    for (int i = 0; i < 4; i++)
#pragma unroll
        for (int j = 0; j < 4; j++) acc[i][j] = 0ULL;

    const int lrow = tid >> 1;            // 0..63
    const int lcol = (tid & 1) * 8;       // 0 or 8
    const float* Ap = inp + (size_t)t * Bn * Dn + (size_t)lrow * Dn + lcol;
    const float* Bp = win + (size_t)rt * 64 * Dn + (size_t)lrow * Dn + lcol;

    for (int kk = 0; kk < Dn; kk += 16) {
        float4 a0 = *(const float4*)(Ap + kk);
        float4 a1 = *(const float4*)(Ap + kk + 4);
        float4 b0 = *(const float4*)(Bp + kk);
        float4 b1 = *(const float4*)(Bp + kk + 4);
        __syncthreads();
        As[lcol + 0][lrow] = a0.x; As[lcol + 1][lrow] = a0.y;
        As[lcol + 2][lrow] = a0.z; As[lcol + 3][lrow] = a0.w;
        As[lcol + 4][lrow] = a1.x; As[lcol + 5][lrow] = a1.y;
        As[lcol + 6][lrow] = a1.z; As[lcol + 7][lrow] = a1.w;
        Bs[lcol + 0][lrow] = b0.x; Bs[lcol + 1][lrow] = b0.y;
        Bs[lcol + 2][lrow] = b0.z; Bs[lcol + 3][lrow] = b0.w;
        Bs[lcol + 4][lrow] = b1.x; Bs[lcol + 5][lrow] = b1.y;
        Bs[lcol + 6][lrow] = b1.z; Bs[lcol + 7][lrow] = b1.w;
        __syncthreads();
#pragma unroll
        for (int k = 0; k < 16; k++) {
            float4 av = *(const float4*)&As[k][tx * 4];
            unsigned long long ad0 = pack2(av.x, av.x);
            unsigned long long ad1 = pack2(av.y, av.y);
            unsigned long long ad2 = pack2(av.z, av.z);
            unsigned long long ad3 = pack2(av.w, av.w);
            ulonglong2 w0 = *(const ulonglong2*)&Bs[k][ty * 8];
            ulonglong2 w1 = *(const ulonglong2*)&Bs[k][ty * 8 + 4];
            ffma2(acc[0][0], ad0, w0.x); ffma2(acc[0][1], ad0, w0.y);
            ffma2(acc[0][2], ad0, w1.x); ffma2(acc[0][3], ad0, w1.y);
            ffma2(acc[1][0], ad1, w0.x); ffma2(acc[1][1], ad1, w0.y);
            ffma2(acc[1][2], ad1, w1.x); ffma2(acc[1][3], ad1, w1.y);
            ffma2(acc[2][0], ad2, w0.x); ffma2(acc[2][1], ad2, w0.y);
            ffma2(acc[2][2], ad2, w1.x); ffma2(acc[2][3], ad2, w1.y);
            ffma2(acc[3][0], ad3, w0.x); ffma2(acc[3][1], ad3, w0.y);
            ffma2(acc[3][2], ad3, w1.x); ffma2(acc[3][3], ad3, w1.y);
        }
    }

    // epilogue: c[bb][j] + bias -> g_P[t][r][b]
    float c[4][8];
#pragma unroll
    for (int bb = 0; bb < 4; bb++)
#pragma unroll
        for (int rp = 0; rp < 4; rp++) {
            float lo, hi;
            unpack2(acc[bb][rp], lo, hi);
            c[bb][rp * 2] = lo;
            c[bb][rp * 2 + 1] = hi;
        }
#pragma unroll
    for (int j = 0; j < 8; j++) {
        int r = rt * 64 + ty * 8 + j;
        float bv = bias[r];
        float4 o = make_float4(c[0][j] + bv, c[1][j] + bv, c[2][j] + bv, c[3][j] + bv);
        *(float4*)&g_P[((size_t)t * Rn + r) * Bn + tx * 4] = o;
    }
}

// ---------------------------------------------------------------------------
// one recurrence step: pre[r][b] = P[t][r][b] + sum_k Wres[r][k]*xT[k][b]
// x_new = mask * (0.5*x_old + 0.5*tanh(pre));  write state + states output.
// grid 128 (16 r-rows each), block 256 (64 b x 4 r-quads), packed f32x2.
// ---------------------------------------------------------------------------
__global__ __launch_bounds__(256) void step_kernel(const float* __restrict__ wres,
                                                   const int* __restrict__ lengths,
                                                   float* __restrict__ out,
                                                   int t) {
    __shared__ __align__(16) float Xs[32 * 64];   // [k][b]
    __shared__ __align__(16) float Ws[32][16];    // [k][rr]
    const int rt  = blockIdx.x;       // 0..127
    const int tid = threadIdx.x;
    const int b   = tid & 63;
    const int rq  = tid >> 6;         // 0..3 -> r = rt*16 + rq*4 + j

    const float* xsrc = (t & 1) ? g_x1 : g_x0;
    float*       xdst = (t & 1) ? g_x0 : g_x1;
    const float* P_t  = g_P + (size_t)t * Rn * Bn;

    unsigned long long acc0 = 0ULL, acc1 = 0ULL;

    const int wr = tid >> 4;              // 0..15 row within tile
    const int wk = (tid & 15) * 2;        // 0..30 k offset
    const float* wp = wres + (size_t)(rt * 16 + wr) * Rn + wk;

    for (int k0 = 0; k0 < Rn; k0 += 32) {
        const float4* xin = (const float4*)(xsrc + k0 * Bn);
        float4 xa = xin[tid];
        float4 xb = xin[tid + 256];
        float2 wv = *(const float2*)(wp + k0);
        __syncthreads();
        ((float4*)Xs)[tid]       = xa;
        ((float4*)Xs)[tid + 256] = xb;
        Ws[wk][wr]     = wv.x;
        Ws[wk + 1][wr] = wv.y;
        __syncthreads();
#pragma unroll
        for (int k = 0; k < 32; k++) {
            float xv = Xs[k * 64 + b];
            unsigned long long xd = pack2(xv, xv);
            ulonglong2 w = *(const ulonglong2*)&Ws[k][rq * 4];
            ffma2(acc0, xd, w.x);
            ffma2(acc1, xd, w.y);
        }
    }

    float s[4];
    unpack2(acc0, s[0], s[1]);
    unpack2(acc1, s[2], s[3]);

    const int len = lengths[b];
    const float m = (len > t) ? 0.5f : 0.0f;   // mask * lr, with lr = 1-lr = 0.5
    const int rbase = rt * 16 + rq * 4;

    float4 ov;
#pragma unroll
    for (int j = 0; j < 4; j++) {
        int r = rbase + j;
        float pre  = s[j] + P_t[(size_t)r * Bn + b];
        float xold = xsrc[(size_t)r * Bn + b];
        float xn   = m * (xold + tanh_acc(pre));
        xdst[(size_t)r * Bn + b] = xn;
        ((float*)&ov)[j] = xn;
    }
    *(float4*)&out[((size_t)b * Tn + t) * Rn + rbase] = ov;
}

// ---------------------------------------------------------------------------
// launch: init + proj + 256 step kernels (all graph-capturable)
// ---------------------------------------------------------------------------
extern "C" void kernel_launch(void* const* d_in, const int* in_sizes, int n_in,
                              void* d_out, int out_size) {
    const float* inp     = (const float*)d_in[0];  // [T,B,D]
    const int*   lengths = (const int*)d_in[1];    // [B]
    const float* win     = (const float*)d_in[2];  // [R,D]
    const float* wres    = (const float*)d_in[3];  // [R,R]
    const float* bias    = (const float*)d_in[4];  // [R]
    const float* x0in    = (const float*)d_in[5];  // [R]
    float* out = (float*)d_out;                    // [B,T,R]

    init_x_kernel<<<(Rn * Bn + 255) / 256, 256>>>(x0in);
    proj_kernel<<<dim3(Rn / 64, Tn), 128>>>(inp, win, bias);
    for (int t = 0; t < Tn; t++) {
        step_kernel<<<128, 256>>>(wres, lengths, out, t);
    }
}

// round 4
// speedup vs baseline: 2.1666x; 2.1666x over previous
#include <cuda_runtime.h>

#define Tn 256
#define Bn 64
#define Dn 768
#define Rn 2048
#define KS 8
#define KC (Rn / KS)   // 256 k per split

// Scratch (static __device__ arrays: allocation-guard safe)
__device__ float g_P[(size_t)Tn * Rn * Bn];   // [t][r][b] : input projection + bias, 128 MB
__device__ float g_x0[Rn * Bn];               // state ping [r][b]
__device__ float g_x1[Rn * Bn];               // state pong [r][b]
__device__ float g_part[KS][Rn][Bn];          // k-split partial sums, 4 MB

// ---- packed f32x2 helpers (Blackwell sm_103a) ----
__device__ __forceinline__ unsigned long long pack2(float lo, float hi) {
    unsigned long long r;
    asm("mov.b64 %0, {%1, %2};" : "=l"(r) : "f"(lo), "f"(hi));
    return r;
}
__device__ __forceinline__ void unpack2(unsigned long long v, float& lo, float& hi) {
    asm("mov.b64 {%0, %1}, %2;" : "=f"(lo), "=f"(hi) : "l"(v));
}
__device__ __forceinline__ void ffma2(unsigned long long& d, unsigned long long a, unsigned long long b) {
    asm("fma.rn.f32x2 %0, %1, %2, %0;" : "+l"(d) : "l"(a), "l"(b));
}

// accurate-enough tanh independent of fast-math flags (~1e-6 rel)
__device__ __forceinline__ float tanh_acc(float x) {
    float ax = fabsf(x);
    float e  = __expf(-2.0f * ax);
    float r  = (1.0f - e) / (1.0f + e);
    return copysignf(r, x);
}

// ---------------------------------------------------------------------------
// init: xT[r][b] = initial_state[r]
// ---------------------------------------------------------------------------
__global__ void init_x_kernel(const float* __restrict__ init_state) {
    int i = blockIdx.x * blockDim.x + threadIdx.x;
    if (i < Rn * Bn) g_x0[i] = init_state[i >> 6];
}

// ---------------------------------------------------------------------------
// proj: g_P[t][r][b] = sum_d inp[t][b][d] * Win[r][d] + bias[r]
// grid (Rn/64, Tn), block 128. Tile 64b x 64r, micro 4b x 8r, packed f32x2.
// ---------------------------------------------------------------------------
__global__ __launch_bounds__(128) void proj_kernel(const float* __restrict__ inp,
                                                   const float* __restrict__ win,
                                                   const float* __restrict__ bias) {
    __shared__ __align__(16) float As[16][64];   // [k][b]
    __shared__ __align__(16) float Bs[16][64];   // [k][r]
    const int t  = blockIdx.y;
    const int rt = blockIdx.x;
    const int tid = threadIdx.x;
    const int tx = tid & 15;        // b-group: b = tx*4 + bb
    const int ty = tid >> 4;        // r-group: r = ty*8 + j  (0..7)

    unsigned long long acc[4][4];
#pragma unroll
    for (int i = 0; i < 4; i++)
#pragma unroll
        for (int j = 0; j < 4; j++) acc[i][j] = 0ULL;

    const int lrow = tid >> 1;            // 0..63
    const int lcol = (tid & 1) * 8;       // 0 or 8
    const float* Ap = inp + (size_t)t * Bn * Dn + (size_t)lrow * Dn + lcol;
    const float* Bp = win + (size_t)rt * 64 * Dn + (size_t)lrow * Dn + lcol;

    for (int kk = 0; kk < Dn; kk += 16) {
        float4 a0 = *(const float4*)(Ap + kk);
        float4 a1 = *(const float4*)(Ap + kk + 4);
        float4 b0 = *(const float4*)(Bp + kk);
        float4 b1 = *(const float4*)(Bp + kk + 4);
        __syncthreads();
        As[lcol + 0][lrow] = a0.x; As[lcol + 1][lrow] = a0.y;
        As[lcol + 2][lrow] = a0.z; As[lcol + 3][lrow] = a0.w;
        As[lcol + 4][lrow] = a1.x; As[lcol + 5][lrow] = a1.y;
        As[lcol + 6][lrow] = a1.z; As[lcol + 7][lrow] = a1.w;
        Bs[lcol + 0][lrow] = b0.x; Bs[lcol + 1][lrow] = b0.y;
        Bs[lcol + 2][lrow] = b0.z; Bs[lcol + 3][lrow] = b0.w;
        Bs[lcol + 4][lrow] = b1.x; Bs[lcol + 5][lrow] = b1.y;
        Bs[lcol + 6][lrow] = b1.z; Bs[lcol + 7][lrow] = b1.w;
        __syncthreads();
#pragma unroll
        for (int k = 0; k < 16; k++) {
            float4 av = *(const float4*)&As[k][tx * 4];
            unsigned long long ad0 = pack2(av.x, av.x);
            unsigned long long ad1 = pack2(av.y, av.y);
            unsigned long long ad2 = pack2(av.z, av.z);
            unsigned long long ad3 = pack2(av.w, av.w);
            ulonglong2 w0 = *(const ulonglong2*)&Bs[k][ty * 8];
            ulonglong2 w1 = *(const ulonglong2*)&Bs[k][ty * 8 + 4];
            ffma2(acc[0][0], ad0, w0.x); ffma2(acc[0][1], ad0, w0.y);
            ffma2(acc[0][2], ad0, w1.x); ffma2(acc[0][3], ad0, w1.y);
            ffma2(acc[1][0], ad1, w0.x); ffma2(acc[1][1], ad1, w0.y);
            ffma2(acc[1][2], ad1, w1.x); ffma2(acc[1][3], ad1, w1.y);
            ffma2(acc[2][0], ad2, w0.x); ffma2(acc[2][1], ad2, w0.y);
            ffma2(acc[2][2], ad2, w1.x); ffma2(acc[2][3], ad2, w1.y);
            ffma2(acc[3][0], ad3, w0.x); ffma2(acc[3][1], ad3, w0.y);
            ffma2(acc[3][2], ad3, w1.x); ffma2(acc[3][3], ad3, w1.y);
        }
    }

    float c[4][8];
#pragma unroll
    for (int bb = 0; bb < 4; bb++)
#pragma unroll
        for (int rp = 0; rp < 4; rp++) {
            float lo, hi;
            unpack2(acc[bb][rp], lo, hi);
            c[bb][rp * 2] = lo;
            c[bb][rp * 2 + 1] = hi;
        }
#pragma unroll
    for (int j = 0; j < 8; j++) {
        int r = rt * 64 + ty * 8 + j;
        float bv = bias[r];
        float4 o = make_float4(c[0][j] + bv, c[1][j] + bv, c[2][j] + bv, c[3][j] + bv);
        *(float4*)&g_P[((size_t)t * Rn + r) * Bn + tx * 4] = o;
    }
}

// ---------------------------------------------------------------------------
// recurrence partial: g_part[ks][r][b] = sum_{k in slice ks} Wres[r][k]*xT[k][b]
// grid (64 r-tiles of 32, 8 k-slices) = 512 CTAs, block 128.
// Thread tile: 4b x 4r -> 8 independent f32x2 acc chains; inner loop
// 2 LDS.128 + 4 pack + 8 ffma2 per k (fma-bound mix).
// ---------------------------------------------------------------------------
__global__ __launch_bounds__(128) void part_kernel(const float* __restrict__ wres, int t) {
    __shared__ __align__(16) float Xs[32][64];   // [k][b]
    __shared__ __align__(16) float Ws[32][32];   // [k][r]
    const int rt  = blockIdx.x;    // 0..63
    const int ks  = blockIdx.y;    // 0..7
    const int tid = threadIdx.x;
    const int bg  = tid & 15;      // b = bg*4 + bb
    const int rg  = tid >> 4;      // r = rt*32 + rg*4 + j  (rg 0..7)

    const float* xsrc = (t & 1) ? g_x1 : g_x0;
    const int r0 = rt * 32;
    const int k0base = ks * KC;

    unsigned long long acc[4][2];
#pragma unroll
    for (int i = 0; i < 4; i++) { acc[i][0] = 0ULL; acc[i][1] = 0ULL; }

    // loader mapping: 32 W-rows x 32 k per chunk
    const int lr = tid >> 2;            // 0..31 : W row within tile
    const int lk = (tid & 3) * 8;       // 0,8,16,24 : k offset
    const float* wp = wres + (size_t)(r0 + lr) * Rn + k0base + lk;

    for (int kc = 0; kc < KC; kc += 32) {
        const float* xg = xsrc + (size_t)(k0base + kc) * Bn;
        float4 xv0 = ((const float4*)xg)[tid];
        float4 xv1 = ((const float4*)xg)[tid + 128];
        float4 xv2 = ((const float4*)xg)[tid + 256];
        float4 xv3 = ((const float4*)xg)[tid + 384];
        float4 w0 = *(const float4*)(wp + kc);
        float4 w1 = *(const float4*)(wp + kc + 4);
        __syncthreads();
        ((float4*)Xs)[tid]       = xv0;
        ((float4*)Xs)[tid + 128] = xv1;
        ((float4*)Xs)[tid + 256] = xv2;
        ((float4*)Xs)[tid + 384] = xv3;
        Ws[lk + 0][lr] = w0.x; Ws[lk + 1][lr] = w0.y;
        Ws[lk + 2][lr] = w0.z; Ws[lk + 3][lr] = w0.w;
        Ws[lk + 4][lr] = w1.x; Ws[lk + 5][lr] = w1.y;
        Ws[lk + 6][lr] = w1.z; Ws[lk + 7][lr] = w1.w;
        __syncthreads();
#pragma unroll
        for (int k = 0; k < 32; k++) {
            float4 xq = *(const float4*)&Xs[k][bg * 4];
            unsigned long long a0 = pack2(xq.x, xq.x);
            unsigned long long a1 = pack2(xq.y, xq.y);
            unsigned long long a2 = pack2(xq.z, xq.z);
            unsigned long long a3 = pack2(xq.w, xq.w);
            ulonglong2 w = *(const ulonglong2*)&Ws[k][rg * 4];
            ffma2(acc[0][0], a0, w.x); ffma2(acc[0][1], a0, w.y);
            ffma2(acc[1][0], a1, w.x); ffma2(acc[1][1], a1, w.y);
            ffma2(acc[2][0], a2, w.x); ffma2(acc[2][1], a2, w.y);
            ffma2(acc[3][0], a3, w.x); ffma2(acc[3][1], a3, w.y);
        }
    }

    // unpack: s[bb][j] = partial for (b = bg*4+bb, r = r0+rg*4+j)
    float s[4][4];
#pragma unroll
    for (int bb = 0; bb < 4; bb++) {
        unpack2(acc[bb][0], s[bb][0], s[bb][1]);
        unpack2(acc[bb][1], s[bb][2], s[bb][3]);
    }
#pragma unroll
    for (int j = 0; j < 4; j++) {
        float4 o = make_float4(s[0][j], s[1][j], s[2][j], s[3][j]);
        *(float4*)&g_part[ks][r0 + rg * 4 + j][bg * 4] = o;
    }
}

// ---------------------------------------------------------------------------
// reduce + epilogue: sum KS partials + P, tanh, leak, mask, write state + out.
// grid 128 (16 r each), block 256 (64 b x 4 r-quads). Fixed summation order
// -> deterministic.
// ---------------------------------------------------------------------------
__global__ __launch_bounds__(256) void reduce_kernel(const int* __restrict__ lengths,
                                                     float* __restrict__ out,
                                                     int t) {
    const int rt  = blockIdx.x;       // 0..127
    const int tid = threadIdx.x;
    const int b   = tid & 63;
    const int rq  = tid >> 6;

    const float* xsrc = (t & 1) ? g_x1 : g_x0;
    float*       xdst = (t & 1) ? g_x0 : g_x1;
    const float* P_t  = g_P + (size_t)t * Rn * Bn;

    const float m = (lengths[b] > t) ? 0.5f : 0.0f;   // mask * lr (lr = 1-lr = 0.5)
    const int rbase = rt * 16 + rq * 4;

    float4 ov;
#pragma unroll
    for (int j = 0; j < 4; j++) {
        const int r = rbase + j;
        float s = P_t[(size_t)r * Bn + b];
#pragma unroll
        for (int ksi = 0; ksi < KS; ksi++) s += g_part[ksi][r][b];
        float xold = xsrc[(size_t)r * Bn + b];
        float xn   = m * (xold + tanh_acc(s));
        xdst[(size_t)r * Bn + b] = xn;
        ((float*)&ov)[j] = xn;
    }
    *(float4*)&out[((size_t)b * Tn + t) * Rn + rbase] = ov;
}

// ---------------------------------------------------------------------------
// launch: init + proj + 256 x (part, reduce) — all graph-capturable
// ---------------------------------------------------------------------------
extern "C" void kernel_launch(void* const* d_in, const int* in_sizes, int n_in,
                              void* d_out, int out_size) {
    const float* inp     = (const float*)d_in[0];  // [T,B,D]
    const int*   lengths = (const int*)d_in[1];    // [B]
    const float* win     = (const float*)d_in[2];  // [R,D]
    const float* wres    = (const float*)d_in[3];  // [R,R]
    const float* bias    = (const float*)d_in[4];  // [R]
    const float* x0in    = (const float*)d_in[5];  // [R]
    float* out = (float*)d_out;                    // [B,T,R]

    init_x_kernel<<<(Rn * Bn + 255) / 256, 256>>>(x0in);
    proj_kernel<<<dim3(Rn / 64, Tn), 128>>>(inp, win, bias);
    for (int t = 0; t < Tn; t++) {
        part_kernel<<<dim3(64, KS), 128>>>(wres, t);
        reduce_kernel<<<128, 256>>>(lengths, out, t);
    }
}